// round 2
// baseline (speedup 1.0000x reference)
#include <cuda_runtime.h>
#include <cstdint>

// Fixed problem shapes
#define BB   32      // batch
#define TT   256     // time
#define NST  32      // categorical variables
#define SS   32      // classes per categorical
#define EE   128     // embedding size
// rows = B*T*N = 262144, elements = rows*S = 2^23

// libdevice accurate logf — immune to -use_fast_math substitution, and the
// exact function XLA GPU lowers log.f32 to.
extern "C" __device__ float __nv_logf(float);

__device__ __forceinline__ uint32_t rotl32(uint32_t x, int r) {
    return (x << r) | (x >> (32 - r));
}

// Threefry-2x32, 20 rounds, key = (0, 42)  (jax.random.key(42) -> [0, 42])
// Partitionable layout: per element i, counter = (hi=0, lo=i):
//   x0 = 0 + ks[0], x1 = i + ks[1];  bits = o0 ^ o1
__device__ __forceinline__ uint32_t threefry_bits_partitionable(uint32_t i) {
    const uint32_t k0 = 0u;
    const uint32_t k1 = 42u;
    const uint32_t k2 = 0u ^ 42u ^ 0x1BD11BDAu;
    uint32_t x0 = 0u + k0;   // counts_hi + ks0
    uint32_t x1 = i + k1;    // counts_lo + ks1
#define TF_RND(r) { x0 += x1; x1 = rotl32(x1, (r)); x1 ^= x0; }
    TF_RND(13) TF_RND(15) TF_RND(26) TF_RND(6)   x0 += k1; x1 += k2 + 1u;
    TF_RND(17) TF_RND(29) TF_RND(16) TF_RND(24)  x0 += k2; x1 += k0 + 2u;
    TF_RND(13) TF_RND(15) TF_RND(26) TF_RND(6)   x0 += k0; x1 += k1 + 3u;
    TF_RND(17) TF_RND(29) TF_RND(16) TF_RND(24)  x0 += k1; x1 += k2 + 4u;
    TF_RND(13) TF_RND(15) TF_RND(26) TF_RND(6)   x0 += k2; x1 += k0 + 5u;
#undef TF_RND
    return x0 ^ x1;
}

// bits -> jax uniform(minval=FLT_MIN, maxval=1) -> gumbel, bit-exact vs XLA GPU
__device__ __forceinline__ float gumbel_from_bits(uint32_t bits) {
    float f = __uint_as_float((bits >> 9) | 0x3F800000u) - 1.0f;  // [0,1)
    float u = fmaxf(f, 1.17549435082228750797e-38f);              // FLT_MIN clamp
    return -__nv_logf(-__nv_logf(u));
}

__global__ void __launch_bounds__(256)
categorical_encoder_kernel(const float* __restrict__ x,
                           const float* __restrict__ codebook,
                           float* __restrict__ out) {
    const int gwarp = (blockIdx.x * blockDim.x + threadIdx.x) >> 5;  // 0..131071
    const int lane  = threadIdx.x & 31;

    // each warp handles two adjacent rows r0 = 2*gwarp, r1 = r0+1
    const int r0 = gwarp << 1;
    const int r1 = r0 | 1;
    const uint32_t e0 = (uint32_t)r0 * SS;        // element base of row 0
    const uint32_t e1 = e0 + SS;                  // element base of row 1

    // per-element partitionable threefry bits (two independent calls -> ILP)
    const uint32_t bits0 = threefry_bits_partitionable(e0 + lane);
    const uint32_t bits1 = threefry_bits_partitionable(e1 + lane);

    const float g0 = gumbel_from_bits(bits0);
    const float g1 = gumbel_from_bits(bits1);

    float v0 = g0 + __ldg(&x[e0 + lane]);
    float v1 = g1 + __ldg(&x[e1 + lane]);
    int   i0 = lane;
    int   i1 = lane;

    // butterfly argmax, first-index (lowest s) tiebreak — matches jnp.argmax
#pragma unroll
    for (int off = 16; off > 0; off >>= 1) {
        float ov0 = __shfl_xor_sync(0xFFFFFFFFu, v0, off);
        int   oi0 = __shfl_xor_sync(0xFFFFFFFFu, i0, off);
        if (ov0 > v0 || (ov0 == v0 && oi0 < i0)) { v0 = ov0; i0 = oi0; }
        float ov1 = __shfl_xor_sync(0xFFFFFFFFu, v1, off);
        int   oi1 = __shfl_xor_sync(0xFFFFFFFFu, i1, off);
        if (ov1 > v1 || (ov1 == v1 && oi1 < i1)) { v1 = ov1; i1 = oi1; }
    }

    // STE forward == pure one-hot gather: out row = codebook[n, idx, :]
    const int n0 = r0 & (NST - 1);
    const int n1 = r1 & (NST - 1);
    const float4* src0 = reinterpret_cast<const float4*>(codebook + ((size_t)n0 * SS + i0) * EE);
    const float4* src1 = reinterpret_cast<const float4*>(codebook + ((size_t)n1 * SS + i1) * EE);
    float4* dst0 = reinterpret_cast<float4*>(out + (size_t)r0 * EE);
    float4* dst1 = reinterpret_cast<float4*>(out + (size_t)r1 * EE);
    dst0[lane] = src0[lane];
    dst1[lane] = src1[lane];
}

extern "C" void kernel_launch(void* const* d_in, const int* in_sizes, int n_in,
                              void* d_out, int out_size) {
    // select inputs by size (x: 8388608 elems, codebook: 131072 elems)
    const float* x        = (const float*)d_in[0];
    const float* codebook = (const float*)d_in[1];
    if (n_in >= 2 && in_sizes[0] < in_sizes[1]) {
        x        = (const float*)d_in[1];
        codebook = (const float*)d_in[0];
    }
    float* out = (float*)d_out;   // [32,256,4096] float32

    // rows = 262144, 2 rows/warp, 8 warps/block -> 16384 blocks
    categorical_encoder_kernel<<<16384, 256>>>(x, codebook, out);
}

// round 3
// speedup vs baseline: 1.1916x; 1.1916x over previous
#include <cuda_runtime.h>
#include <cstdint>

// Fixed problem shapes
#define NST  32      // categorical variables
#define SS   32      // classes per categorical
#define EE   128     // embedding size
#define ROWS 262144  // B*T*N = 32*256*32

// libdevice accurate logf — the exact function XLA GPU lowers log.f32 to,
// immune to fast-math substitution.
extern "C" __device__ float __nv_logf(float);

__device__ __forceinline__ uint32_t rotl32(uint32_t x, int r) {
    return (x << r) | (x >> (32 - r));
}

// Threefry-2x32, 20 rounds, key = (0, 42), partitionable layout:
// counter = (hi=0, lo=i); bits = o0 ^ o1.  (Confirmed bit-exact in R2.)
__device__ __forceinline__ uint32_t threefry_bits(uint32_t i) {
    const uint32_t k0 = 0u;
    const uint32_t k1 = 42u;
    const uint32_t k2 = 0u ^ 42u ^ 0x1BD11BDAu;
    uint32_t x0 = 0u + k0;
    uint32_t x1 = i + k1;
#define TF_RND(r) { x0 += x1; x1 = rotl32(x1, (r)); x1 ^= x0; }
    TF_RND(13) TF_RND(15) TF_RND(26) TF_RND(6)   x0 += k1; x1 += k2 + 1u;
    TF_RND(17) TF_RND(29) TF_RND(16) TF_RND(24)  x0 += k2; x1 += k0 + 2u;
    TF_RND(13) TF_RND(15) TF_RND(26) TF_RND(6)   x0 += k0; x1 += k1 + 3u;
    TF_RND(17) TF_RND(29) TF_RND(16) TF_RND(24)  x0 += k1; x1 += k2 + 4u;
    TF_RND(13) TF_RND(15) TF_RND(26) TF_RND(6)   x0 += k2; x1 += k0 + 5u;
#undef TF_RND
    return x0 ^ x1;
}

// bits -> jax uniform(FLT_MIN, 1) -> gumbel, bit-exact vs XLA GPU
__device__ __forceinline__ float gumbel_from_bits(uint32_t bits) {
    float f = __uint_as_float((bits >> 9) | 0x3F800000u) - 1.0f;
    float u = fmaxf(f, 1.17549435082228750797e-38f);
    return -__nv_logf(-__nv_logf(u));
}

// order-preserving float -> uint transform (monotone; equal floats -> equal keys)
__device__ __forceinline__ uint32_t float_ordered(float v) {
    uint32_t b = __float_as_uint(v);
    return b ^ (uint32_t)(((int32_t)b >> 31) | (int32_t)0x80000000);
}

__global__ void __launch_bounds__(256)
categorical_encoder_kernel(const float* __restrict__ x,
                           const float* __restrict__ codebook,
                           float* __restrict__ out) {
    const int gwarp = (blockIdx.x * blockDim.x + threadIdx.x) >> 5;  // 0..65535
    const int lane  = threadIdx.x & 31;

    // 4 rows per warp: rows rbase..rbase+3
    const int rbase = gwarp << 2;
    const uint32_t ebase = ((uint32_t)rbase << 5) + (uint32_t)lane;  // element idx

    // 4 independent threefry calls (ILP against alu latency)
    uint32_t bits[4];
#pragma unroll
    for (int j = 0; j < 4; j++) bits[j] = threefry_bits(ebase + (uint32_t)j * SS);

    float v[4];
#pragma unroll
    for (int j = 0; j < 4; j++)
        v[j] = gumbel_from_bits(bits[j]) + __ldg(&x[ebase + (uint32_t)j * SS]);

#pragma unroll
    for (int j = 0; j < 4; j++) {
        // argmax over lanes via single-instruction redux + first-index tiebreak
        const uint32_t u    = float_ordered(v[j]);
        const uint32_t umax = __reduce_max_sync(0xFFFFFFFFu, u);
        const uint32_t bal  = __ballot_sync(0xFFFFFFFFu, u == umax);
        const int idx = __ffs(bal) - 1;   // lowest lane == lowest s (jnp.argmax)

        // STE forward == one-hot gather: out row = codebook[n, idx, :]
        const int r = rbase + j;
        const int n = r & (NST - 1);
        const float4* src = reinterpret_cast<const float4*>(
            codebook + ((size_t)n * SS + idx) * EE);
        float4* dst = reinterpret_cast<float4*>(out + (size_t)r * EE);
        dst[lane] = src[lane];
    }
}

extern "C" void kernel_launch(void* const* d_in, const int* in_sizes, int n_in,
                              void* d_out, int out_size) {
    // select inputs by size (x: 8388608 elems, codebook: 131072 elems)
    const float* x        = (const float*)d_in[0];
    const float* codebook = (const float*)d_in[1];
    if (n_in >= 2 && in_sizes[0] < in_sizes[1]) {
        x        = (const float*)d_in[1];
        codebook = (const float*)d_in[0];
    }
    float* out = (float*)d_out;

    // 262144 rows, 4 rows/warp, 8 warps/block -> 8192 blocks
    categorical_encoder_kernel<<<8192, 256>>>(x, codebook, out);
}